// round 2
// baseline (speedup 1.0000x reference)
#include <cuda_runtime.h>

#define N_TOKENS 2048   // 8 * 256
#define DIM 128
#define DC 16
#define WARPS_PER_BLOCK 16
#define BLOCK_THREADS (WARPS_PER_BLOCK * 32)
#define GRID_BLOCKS (N_TOKENS / WARPS_PER_BLOCK)   // 128

__global__ void __launch_bounds__(BLOCK_THREADS) flf_quant_warp_kernel(
    const float* __restrict__ x,      // [2048, 128]
    const float* __restrict__ W_in,   // [128, 16]
    const float* __restrict__ b_in,   // [16]
    const float* __restrict__ W_out,  // [16, 128]
    const float* __restrict__ b_out,  // [128]
    float* __restrict__ out,          // [2048*128 (+ 2048 indices)]
    int write_indices)
{
    __shared__ float xs[WARPS_PER_BLOCK][DIM];

    const int warp = threadIdx.x >> 5;
    const int lane = threadIdx.x & 31;
    const int token = blockIdx.x * WARPS_PER_BLOCK + warp;
    const unsigned FULL = 0xFFFFFFFFu;

    // ---- load x row: 32 lanes x float4 = 128 floats, coalesced ----
    float4 xv = reinterpret_cast<const float4*>(x + (size_t)token * DIM)[lane];
    reinterpret_cast<float4*>(xs[warp])[lane] = xv;
    __syncwarp();

    // ---- z_e = x . W_in[:,e] + b_in[e]
    //      lane -> (e = lane&15, half c = lane>>4); 64 FMAs per lane, then one shfl_xor ----
    const int e = lane & 15;
    const int c = lane >> 4;
    const float* xr = xs[warp] + c * 64;
    const float* wi = W_in + (size_t)(c * 64) * DC + e;

    float p0 = 0.0f, p1 = 0.0f, p2 = 0.0f, p3 = 0.0f;
    #pragma unroll
    for (int i = 0; i < 64; i += 4) {
        p0 = fmaf(xr[i    ], wi[(i    ) * DC], p0);
        p1 = fmaf(xr[i + 1], wi[(i + 1) * DC], p1);
        p2 = fmaf(xr[i + 2], wi[(i + 2) * DC], p2);
        p3 = fmaf(xr[i + 3], wi[(i + 3) * DC], p3);
    }
    float ps = (p0 + p1) + (p2 + p3);
    float z = ps + __shfl_xor_sync(FULL, ps, 16) + b_in[e];

    // ---- sign -> index + broadcast signs via ballot (tie z==0 -> bit 0, matches argmin) ----
    unsigned mask = __ballot_sync(FULL, z > 0.0f) & 0xFFFFu;   // bit e = sign of z_e (lanes 16-31 mirror)
    const int idx = (int)(__brev(mask) >> 16);

    // ---- out = sum_e s_e * W_out[e,:] + b_out : lane -> 4 dims, float4 coalesced ----
    float4 o = reinterpret_cast<const float4*>(b_out)[lane];
    const float4* wo = reinterpret_cast<const float4*>(W_out) + lane;   // + e*32 per row
    #pragma unroll
    for (int ee = 0; ee < DC; ee++) {
        const float s = ((mask >> ee) & 1u) ? 1.0f : -1.0f;
        float4 w = wo[ee * (DIM / 4)];
        o.x = fmaf(s, w.x, o.x);
        o.y = fmaf(s, w.y, o.y);
        o.z = fmaf(s, w.z, o.z);
        o.w = fmaf(s, w.w, o.w);
    }
    reinterpret_cast<float4*>(out + (size_t)token * DIM)[lane] = o;

    if (write_indices && lane == 0) {
        out[(size_t)N_TOKENS * DIM + token] = (float)idx;
    }
}

extern "C" void kernel_launch(void* const* d_in, const int* in_sizes, int n_in,
                              void* d_out, int out_size)
{
    const float* x     = (const float*)d_in[0];
    const float* W_in  = (const float*)d_in[1];
    const float* b_in  = (const float*)d_in[2];
    const float* W_out = (const float*)d_in[3];
    const float* b_out = (const float*)d_in[4];
    float* out = (float*)d_out;

    int write_indices = (out_size >= N_TOKENS * DIM + N_TOKENS) ? 1 : 0;

    flf_quant_warp_kernel<<<GRID_BLOCKS, BLOCK_THREADS>>>(
        x, W_in, b_in, W_out, b_out, out, write_indices);
}